// round 5
// baseline (speedup 1.0000x reference)
#include <cuda_runtime.h>
#include <cstdint>

// Problem constants
#define BATCH 4
#define NPTS  200000
#define NGRID 128            // NX = NY = NZ = 128
#define NVOX  (BATCH * NGRID * NGRID * NGRID)   // 8,388,608 voxels
#define NWORDS (NVOX / 32)                      // 262,144 uint32 per tensor

// Scratch: 2 tensors x 1 MB bitmask = 2 MB (static device array, no alloc).
// Invariant: zero at entry to kernel_launch. Zero-initialized at module load;
// expand_kernel re-zeroes each word after consuming it, so every invocation
// (correctness run, each graph replay) starts from the same state.
__device__ unsigned int g_mask[2][NWORDS];

// ---------------------------------------------------------------------------
// Kernel 1: scatter points into occupancy bitmasks.
// grid.y = tensor index t (0 = points_a, 1 = points_b); one thread per point.
//
// Numeric model: XLA fast-math (arcp) hoists the broadcast divisor into a
// correctly-rounded reciprocal:  q = (p - 0.5*v) * (1/v).  Reproduced exactly
// with _rn intrinsics (verified rel_err == 0.0 in R3/R4).
// rintf = round-half-even = jnp.round.
// ---------------------------------------------------------------------------
__device__ __forceinline__ int voxel_coord(float p, float v, float rinv) {
    float half    = __fmul_rn(v, 0.5f);        // exact
    float shifted = __fsub_rn(p, half);        // IEEE sub
    float q       = __fmul_rn(shifted, rinv);  // multiply by CR reciprocal (arcp)
    return (int)rintf(q) + 64;
}

__global__ void scatter_kernel(const float* __restrict__ pts_a,
                               const float* __restrict__ pts_b,
                               const float* __restrict__ vs) {
    unsigned idx = blockIdx.x * blockDim.x + threadIdx.x;  // over BATCH*NPTS
    if (idx >= BATCH * NPTS) return;
    const int t = blockIdx.y;
    const float* __restrict__ pts = (t == 0) ? pts_a : pts_b;

    const int b = idx / NPTS;
    const float vx = __ldg(&vs[b * 3 + 0]);
    const float vy = __ldg(&vs[b * 3 + 1]);
    const float vz = __ldg(&vs[b * 3 + 2]);

    // correctly-rounded reciprocals (IEEE divide; NOT MUFU.RCP)
    const float rx = __fdiv_rn(1.0f, vx);
    const float ry = __fdiv_rn(1.0f, vy);
    const float rz = __fdiv_rn(1.0f, vz);

    const float px = pts[(size_t)idx * 3 + 0];
    const float py = pts[(size_t)idx * 3 + 1];
    const float pz = pts[(size_t)idx * 3 + 2];

    const int i = voxel_coord(px, vx, rx);
    const int j = voxel_coord(py, vy, ry);
    const int k = voxel_coord(pz, vz, rz);

    if ((unsigned)i < NGRID && (unsigned)j < NGRID && (unsigned)k < NGRID) {
        const unsigned lin = (((unsigned)b * NGRID + i) * NGRID + j) * NGRID + k;
        atomicOr(&g_mask[t][lin >> 5], 1u << (lin & 31u));
    }
}

// ---------------------------------------------------------------------------
// Kernel 2: expand bitmasks into output AND clear the mask for the next call.
// out layout: [B, 128, 128, 128, 4] f32 -> one float4 per voxel.
//   c=0,1: occ_a * emb[0][0..1];  c=2,3: occ_b * emb[1][0..1]
// Each thread handles 2 consecutive voxels (32 B of stores, plain write-back
// STG.128 — NOT __stwt, which tanked store BW to 1.6 TB/s in R4).
// Each warp covers exactly 2 mask words; lane 0 / lane 16 clear them after
// the broadcast reads.
// ---------------------------------------------------------------------------
__global__ void expand_kernel(float4* __restrict__ out,
                              const float* __restrict__ emb) {
    const unsigned tid  = blockIdx.x * blockDim.x + threadIdx.x;  // < NVOX/2
    const unsigned lin0 = tid * 2u;            // first of 2 consecutive voxels
    const unsigned w    = lin0 >> 5;           // both voxels share one word
    const unsigned bit  = lin0 & 31u;          // even bit; second voxel = bit+1

    const unsigned wa = g_mask[0][w];
    const unsigned wb = g_mask[1][w];

    __syncwarp();                 // all lanes' reads before the clears
    if ((threadIdx.x & 15u) == 0u) {   // lanes 0 and 16: each clears its word
        g_mask[0][w] = 0u;
        g_mask[1][w] = 0u;
    }

    const float e00 = __ldg(&emb[0]);
    const float e01 = __ldg(&emb[1]);
    const float e10 = __ldg(&emb[2]);
    const float e11 = __ldg(&emb[3]);

    const bool a0 = (wa >> bit) & 1u;
    const bool c0 = (wb >> bit) & 1u;
    const bool a1 = (wa >> (bit + 1u)) & 1u;
    const bool c1 = (wb >> (bit + 1u)) & 1u;

    out[lin0]      = make_float4(a0 ? e00 : 0.0f, a0 ? e01 : 0.0f,
                                 c0 ? e10 : 0.0f, c0 ? e11 : 0.0f);
    out[lin0 + 1u] = make_float4(a1 ? e00 : 0.0f, a1 ? e01 : 0.0f,
                                 c1 ? e10 : 0.0f, c1 ? e11 : 0.0f);
}

// ---------------------------------------------------------------------------
// Launch
// Inputs (metadata order): points_a [4,200000,3] f32, points_b [4,200000,3] f32,
//                          neck_voxel_sizes [4,3] f32, embedding_weight [2,2] f32
// Output: [4,128,128,128,4] f32  (33,554,432 floats)
// ---------------------------------------------------------------------------
extern "C" void kernel_launch(void* const* d_in, const int* in_sizes, int n_in,
                              void* d_out, int out_size) {
    const float* pts_a = (const float*)d_in[0];
    const float* pts_b = (const float*)d_in[1];
    const float* vs    = (const float*)d_in[2];
    const float* emb   = (const float*)d_in[3];
    float4* out        = (float4*)d_out;

    // 1) scatter both point sets (mask is zero on entry by invariant)
    dim3 sgrid((BATCH * NPTS + 255) / 256, 2);
    scatter_kernel<<<sgrid, 256>>>(pts_a, pts_b, vs);

    // 2) expand to output + self-clear mask: NVOX/2 threads, 2 float4 each
    expand_kernel<<<(NVOX / 2) / 256, 256>>>(out, emb);
}

// round 6
// speedup vs baseline: 1.4618x; 1.4618x over previous
#include <cuda_runtime.h>
#include <cstdint>

// Problem constants
#define BATCH 4
#define NPTS  200000
#define NGRID 128            // NX = NY = NZ = 128
#define NVOX  (BATCH * NGRID * NGRID * NGRID)   // 8,388,608 voxels
#define NWORDS (NVOX / 32)                      // 262,144 uint32 per tensor

// Scratch: 2 tensors x 1 MB bitmask = 2 MB (static device array, no alloc).
// Invariant: zero at entry to kernel_launch. Zero-initialized at module load;
// expand_kernel re-zeroes each word after consuming it, so every invocation
// (correctness run, each graph replay) starts from the same state.
__device__ unsigned int g_mask[2][NWORDS];

// ---------------------------------------------------------------------------
// Kernel 1: scatter points into occupancy bitmasks.
// grid.y = tensor index t (0 = points_a, 1 = points_b); one thread per point.
//
// Numeric model: XLA fast-math (arcp) hoists the broadcast divisor into a
// correctly-rounded reciprocal:  q = (p - 0.5*v) * (1/v).  Reproduced exactly
// with _rn intrinsics (verified rel_err == 0.0 in R3/R4/R5).
// rintf = round-half-even = jnp.round.
// ---------------------------------------------------------------------------
__device__ __forceinline__ int voxel_coord(float p, float v, float rinv) {
    float half    = __fmul_rn(v, 0.5f);        // exact
    float shifted = __fsub_rn(p, half);        // IEEE sub
    float q       = __fmul_rn(shifted, rinv);  // multiply by CR reciprocal (arcp)
    return (int)rintf(q) + 64;
}

__global__ void scatter_kernel(const float* __restrict__ pts_a,
                               const float* __restrict__ pts_b,
                               const float* __restrict__ vs) {
    unsigned idx = blockIdx.x * blockDim.x + threadIdx.x;  // over BATCH*NPTS
    if (idx >= BATCH * NPTS) return;
    const int t = blockIdx.y;
    const float* __restrict__ pts = (t == 0) ? pts_a : pts_b;

    const int b = idx / NPTS;
    const float vx = __ldg(&vs[b * 3 + 0]);
    const float vy = __ldg(&vs[b * 3 + 1]);
    const float vz = __ldg(&vs[b * 3 + 2]);

    // correctly-rounded reciprocals (IEEE divide; NOT MUFU.RCP)
    const float rx = __fdiv_rn(1.0f, vx);
    const float ry = __fdiv_rn(1.0f, vy);
    const float rz = __fdiv_rn(1.0f, vz);

    const float px = pts[(size_t)idx * 3 + 0];
    const float py = pts[(size_t)idx * 3 + 1];
    const float pz = pts[(size_t)idx * 3 + 2];

    const int i = voxel_coord(px, vx, rx);
    const int j = voxel_coord(py, vy, ry);
    const int k = voxel_coord(pz, vz, rz);

    if ((unsigned)i < NGRID && (unsigned)j < NGRID && (unsigned)k < NGRID) {
        const unsigned lin = (((unsigned)b * NGRID + i) * NGRID + j) * NGRID + k;
        atomicOr(&g_mask[t][lin >> 5], 1u << (lin & 31u));
    }
}

// ---------------------------------------------------------------------------
// Kernel 2: expand bitmasks into output AND clear the mask for the next call.
// out layout: [B, 128, 128, 128, 4] f32 -> one float4 per voxel.
//   c=0,1: occ_a * emb[0][0..1];  c=2,3: occ_b * emb[1][0..1]
//
// Store pattern (the critical part): each warp owns 128 CONSECUTIVE voxels.
// Thread element u accesses voxel base + u*32 + lane, so every STG.128 has
// lane-contiguous 16 B addresses -> full 512 B written per instruction
// (R5's 2-consecutive-per-thread layout produced half-filled cache lines and
// halved store BW; __stwt in R4 was a separate regression. Both reverted.)
// Warp covers exactly 4 mask words (bit index == lane); lanes 0-7 clear the
// 8 words (2 tensors x 4) after the broadcast reads.
// ---------------------------------------------------------------------------
__global__ void expand_kernel(float4* __restrict__ out,
                              const float* __restrict__ emb) {
    const unsigned gwarp = (blockIdx.x * blockDim.x + threadIdx.x) >> 5;
    const unsigned lane  = threadIdx.x & 31u;
    const unsigned base  = gwarp * 128u;     // first voxel of this warp
    const unsigned w0    = base >> 5;        // first of 4 mask words

    // Broadcast reads: all lanes read the same word per u (L1 broadcast, N=1)
    unsigned wa[4], wb[4];
#pragma unroll
    for (int u = 0; u < 4; u++) {
        wa[u] = g_mask[0][w0 + u];
        wb[u] = g_mask[1][w0 + u];
    }

    __syncwarp();                        // all reads before the clears
    if (lane < 4u)        g_mask[0][w0 + lane]      = 0u;
    else if (lane < 8u)   g_mask[1][w0 + lane - 4u] = 0u;

    const float e00 = __ldg(&emb[0]);
    const float e01 = __ldg(&emb[1]);
    const float e10 = __ldg(&emb[2]);
    const float e11 = __ldg(&emb[3]);

#pragma unroll
    for (int u = 0; u < 4; u++) {
        const bool a = (wa[u] >> lane) & 1u;
        const bool c = (wb[u] >> lane) & 1u;
        out[base + (unsigned)u * 32u + lane] =
            make_float4(a ? e00 : 0.0f, a ? e01 : 0.0f,
                        c ? e10 : 0.0f, c ? e11 : 0.0f);
    }
}

// ---------------------------------------------------------------------------
// Launch
// Inputs (metadata order): points_a [4,200000,3] f32, points_b [4,200000,3] f32,
//                          neck_voxel_sizes [4,3] f32, embedding_weight [2,2] f32
// Output: [4,128,128,128,4] f32  (33,554,432 floats)
// ---------------------------------------------------------------------------
extern "C" void kernel_launch(void* const* d_in, const int* in_sizes, int n_in,
                              void* d_out, int out_size) {
    const float* pts_a = (const float*)d_in[0];
    const float* pts_b = (const float*)d_in[1];
    const float* vs    = (const float*)d_in[2];
    const float* emb   = (const float*)d_in[3];
    float4* out        = (float4*)d_out;

    // 1) scatter both point sets (mask is zero on entry by invariant)
    dim3 sgrid((BATCH * NPTS + 255) / 256, 2);
    scatter_kernel<<<sgrid, 256>>>(pts_a, pts_b, vs);

    // 2) expand + self-clear: NVOX/128 warps, each thread 4 float4s
    //    threads = NVOX/4 ; blocks = NVOX/4/256 = 8192
    expand_kernel<<<(NVOX / 4) / 256, 256>>>(out, emb);
}

// round 7
// speedup vs baseline: 1.8500x; 1.2655x over previous
#include <cuda_runtime.h>
#include <cstdint>

// Problem constants
#define BATCH 4
#define NPTS  200000
#define NGRID 128            // NX = NY = NZ = 128
#define NVOX  (BATCH * NGRID * NGRID * NGRID)   // 8,388,608 voxels

// ---------------------------------------------------------------------------
// Kernel 1: zero-fill the output tensor (134 MB). Pure streaming stores,
// one float4 per thread, lane-contiguous (the R3-proven fast pattern).
// ---------------------------------------------------------------------------
__global__ void fill_kernel(float4* __restrict__ out) {
    const unsigned idx = blockIdx.x * blockDim.x + threadIdx.x;  // < NVOX
    out[idx] = make_float4(0.0f, 0.0f, 0.0f, 0.0f);
}

// ---------------------------------------------------------------------------
// Kernel 2: scatter points, writing embedding values DIRECTLY into the output.
// grid.y = tensor index t (0 = points_a -> channels 0,1 ; 1 = points_b -> 2,3).
// One thread per point. No atomics: all writers to a given 8 B slot write the
// identical constant value, so the race is value-deterministic.
//
// Numeric model: XLA fast-math (arcp) hoists the broadcast divisor into a
// correctly-rounded reciprocal:  q = (p - 0.5*v) * (1/v).  Reproduced exactly
// with _rn intrinsics (verified rel_err == 0.0 in R3-R6).
// rintf = round-half-even = jnp.round.
// ---------------------------------------------------------------------------
__device__ __forceinline__ int voxel_coord(float p, float v, float rinv) {
    float half    = __fmul_rn(v, 0.5f);        // exact
    float shifted = __fsub_rn(p, half);        // IEEE sub
    float q       = __fmul_rn(shifted, rinv);  // multiply by CR reciprocal (arcp)
    return (int)rintf(q) + 64;
}

__global__ void scatter_kernel(const float* __restrict__ pts_a,
                               const float* __restrict__ pts_b,
                               const float* __restrict__ vs,
                               const float* __restrict__ emb,
                               float2* __restrict__ out2) {
    unsigned idx = blockIdx.x * blockDim.x + threadIdx.x;  // over BATCH*NPTS
    if (idx >= BATCH * NPTS) return;
    const int t = blockIdx.y;
    const float* __restrict__ pts = (t == 0) ? pts_a : pts_b;

    const int b = idx / NPTS;
    const float vx = __ldg(&vs[b * 3 + 0]);
    const float vy = __ldg(&vs[b * 3 + 1]);
    const float vz = __ldg(&vs[b * 3 + 2]);

    // correctly-rounded reciprocals (IEEE divide; NOT MUFU.RCP)
    const float rx = __fdiv_rn(1.0f, vx);
    const float ry = __fdiv_rn(1.0f, vy);
    const float rz = __fdiv_rn(1.0f, vz);

    const float px = pts[(size_t)idx * 3 + 0];
    const float py = pts[(size_t)idx * 3 + 1];
    const float pz = pts[(size_t)idx * 3 + 2];

    const int i = voxel_coord(px, vx, rx);
    const int j = voxel_coord(py, vy, ry);
    const int k = voxel_coord(pz, vz, rz);

    if ((unsigned)i < NGRID && (unsigned)j < NGRID && (unsigned)k < NGRID) {
        const unsigned lin = (((unsigned)b * NGRID + i) * NGRID + j) * NGRID + k;
        const float e0 = __ldg(&emb[t * 2 + 0]);
        const float e1 = __ldg(&emb[t * 2 + 1]);
        // out[lin] is a float4; tensor t owns its float2 half (t=0 -> .xy, t=1 -> .zw)
        out2[lin * 2u + (unsigned)t] = make_float2(e0, e1);
    }
}

// ---------------------------------------------------------------------------
// Launch
// Inputs (metadata order): points_a [4,200000,3] f32, points_b [4,200000,3] f32,
//                          neck_voxel_sizes [4,3] f32, embedding_weight [2,2] f32
// Output: [4,128,128,128,4] f32  (33,554,432 floats)
// ---------------------------------------------------------------------------
extern "C" void kernel_launch(void* const* d_in, const int* in_sizes, int n_in,
                              void* d_out, int out_size) {
    const float* pts_a = (const float*)d_in[0];
    const float* pts_b = (const float*)d_in[1];
    const float* vs    = (const float*)d_in[2];
    const float* emb   = (const float*)d_in[3];

    // 1) zero-fill output: NVOX float4 stores
    fill_kernel<<<NVOX / 256, 256>>>((float4*)d_out);

    // 2) scatter both point sets directly into the output
    dim3 sgrid((BATCH * NPTS + 255) / 256, 2);
    scatter_kernel<<<sgrid, 256>>>(pts_a, pts_b, vs, emb, (float2*)d_out);
}

// round 8
// speedup vs baseline: 1.9484x; 1.0532x over previous
#include <cuda_runtime.h>
#include <cstdint>

// Problem constants
#define BATCH 4
#define NPTS  200000
#define NGRID 128            // NX = NY = NZ = 128
#define NVOX  (BATCH * NGRID * NGRID * NGRID)   // 8,388,608 voxels
#define NWORDS (NVOX / 32)                      // 262,144 uint32 per tensor

// Scratch (static device arrays, no alloc):
__device__ unsigned int g_mask[2][NWORDS];   // 2 MB occupancy bitmasks
__device__ float g_recip[BATCH][3];          // precomputed 1/v (CR)
__device__ float g_emb[4];                   // embedding values

// ---------------------------------------------------------------------------
// Kernel 1: setup — zero both bitmasks (2 MB, uint4 stores) AND precompute
// the 12 correctly-rounded reciprocals + 4 embedding scalars.
// __fdiv_rn(1,v) here == the per-thread value used in R3-R7 -> bit-identical.
// ---------------------------------------------------------------------------
__global__ void setup_kernel(const float* __restrict__ vs,
                             const float* __restrict__ emb) {
    const unsigned idx = blockIdx.x * blockDim.x + threadIdx.x;  // < 131072
    ((uint4*)g_mask)[idx] = make_uint4(0u, 0u, 0u, 0u);
    if (blockIdx.x == 0) {
        if (threadIdx.x < 12u)
            ((float*)g_recip)[threadIdx.x] = __fdiv_rn(1.0f, vs[threadIdx.x]);
        else if (threadIdx.x >= 16u && threadIdx.x < 20u)
            g_emb[threadIdx.x - 16u] = emb[threadIdx.x - 16u];
    }
}

// ---------------------------------------------------------------------------
// Kernel 2: scatter points into occupancy bitmasks (atomicOr, L2-resident).
// grid.y = tensor index t; one thread per point. No divides in the hot path.
//
// Numeric model (verified rel_err == 0.0): XLA arcp form
//   q = (p - 0.5*v) * (1/v),  with 1/v correctly rounded.
// rintf = round-half-even = jnp.round.
// ---------------------------------------------------------------------------
__device__ __forceinline__ int voxel_coord(float p, float v, float rinv) {
    float half    = __fmul_rn(v, 0.5f);        // exact
    float shifted = __fsub_rn(p, half);        // IEEE sub
    float q       = __fmul_rn(shifted, rinv);  // multiply by CR reciprocal
    return (int)rintf(q) + 64;
}

__global__ void scatter_kernel(const float* __restrict__ pts_a,
                               const float* __restrict__ pts_b,
                               const float* __restrict__ vs) {
    unsigned idx = blockIdx.x * blockDim.x + threadIdx.x;  // over BATCH*NPTS
    if (idx >= BATCH * NPTS) return;
    const int t = blockIdx.y;
    const float* __restrict__ pts = (t == 0) ? pts_a : pts_b;

    const int b = idx / NPTS;
    const float vx = __ldg(&vs[b * 3 + 0]);
    const float vy = __ldg(&vs[b * 3 + 1]);
    const float vz = __ldg(&vs[b * 3 + 2]);
    const float rx = g_recip[b][0];
    const float ry = g_recip[b][1];
    const float rz = g_recip[b][2];

    const float px = pts[(size_t)idx * 3 + 0];
    const float py = pts[(size_t)idx * 3 + 1];
    const float pz = pts[(size_t)idx * 3 + 2];

    const int i = voxel_coord(px, vx, rx);
    const int j = voxel_coord(py, vy, ry);
    const int k = voxel_coord(pz, vz, rz);

    if ((unsigned)i < NGRID && (unsigned)j < NGRID && (unsigned)k < NGRID) {
        const unsigned lin = (((unsigned)b * NGRID + i) * NGRID + j) * NGRID + k;
        atomicOr(&g_mask[t][lin >> 5], 1u << (lin & 31u));
    }
}

// ---------------------------------------------------------------------------
// Kernel 3: expand bitmasks into the output tensor. Mirrors R7's fill kernel
// (one float4 per thread, lane-contiguous STG.128 -> full 512 B per warp
// instruction, measured ~7 TB/s) + 2 broadcast mask loads per warp + selects.
// NO mask clears here (fused clears measured toxic in R4-R6), no __stwt.
// ---------------------------------------------------------------------------
__global__ void expand_kernel(float4* __restrict__ out) {
    const unsigned lin = blockIdx.x * blockDim.x + threadIdx.x;  // < NVOX
    const unsigned w   = lin >> 5;
    const unsigned bit = lin & 31u;

    const unsigned wa = g_mask[0][w];   // broadcast within warp
    const unsigned wb = g_mask[1][w];

    const float e00 = g_emb[0];
    const float e01 = g_emb[1];
    const float e10 = g_emb[2];
    const float e11 = g_emb[3];

    const bool a = (wa >> bit) & 1u;
    const bool c = (wb >> bit) & 1u;

    out[lin] = make_float4(a ? e00 : 0.0f,
                           a ? e01 : 0.0f,
                           c ? e10 : 0.0f,
                           c ? e11 : 0.0f);
}

// ---------------------------------------------------------------------------
// Launch
// Inputs (metadata order): points_a [4,200000,3] f32, points_b [4,200000,3] f32,
//                          neck_voxel_sizes [4,3] f32, embedding_weight [2,2] f32
// Output: [4,128,128,128,4] f32  (33,554,432 floats)
// ---------------------------------------------------------------------------
extern "C" void kernel_launch(void* const* d_in, const int* in_sizes, int n_in,
                              void* d_out, int out_size) {
    const float* pts_a = (const float*)d_in[0];
    const float* pts_b = (const float*)d_in[1];
    const float* vs    = (const float*)d_in[2];
    const float* emb   = (const float*)d_in[3];

    // 1) setup: zero 2 MB mask (131072 uint4) + precompute recips/emb
    setup_kernel<<<131072 / 256, 256>>>(vs, emb);

    // 2) scatter both point sets into the bitmasks
    dim3 sgrid((BATCH * NPTS + 255) / 256, 2);
    scatter_kernel<<<sgrid, 256>>>(pts_a, pts_b, vs);

    // 3) expand to output: NVOX float4 stores
    expand_kernel<<<NVOX / 256, 256>>>((float4*)d_out);
}

// round 9
// speedup vs baseline: 2.2763x; 1.1683x over previous
#include <cuda_runtime.h>
#include <cstdint>

// Problem constants
#define BATCH 4
#define NPTS  200000
#define NGRID 128            // NX = NY = NZ = 128
#define NVOX  (BATCH * NGRID * NGRID * NGRID)   // 8,388,608 voxels
#define NWORDS (NVOX / 32)                      // 262,144 uint32 per tensor

// Scratch (static device arrays, no alloc):
__device__ unsigned int g_mask[2][NWORDS];   // 2 MB occupancy bitmasks
__device__ float g_recip[BATCH][3];          // precomputed 1/v (CR)

// ---------------------------------------------------------------------------
// Kernel 1: setup — zero both bitmasks (2 MB, uint4 stores) AND precompute
// the 12 correctly-rounded reciprocals.
// (Measured: ~4.5 us dominated by first-kernel-in-graph ramp, not work.)
// ---------------------------------------------------------------------------
__global__ void setup_kernel(const float* __restrict__ vs) {
    const unsigned idx = blockIdx.x * blockDim.x + threadIdx.x;  // < 131072
    ((uint4*)g_mask)[idx] = make_uint4(0u, 0u, 0u, 0u);
    if (blockIdx.x == 0 && threadIdx.x < 12u)
        ((float*)g_recip)[threadIdx.x] = __fdiv_rn(1.0f, vs[threadIdx.x]);
}

// ---------------------------------------------------------------------------
// Kernel 2: scatter points into occupancy bitmasks (atomicOr, L2-resident).
// grid.y = tensor index t; one thread per point.
//
// Numeric model (verified rel_err == 0.0 since R3): XLA arcp form
//   q = (p - 0.5*v) * (1/v),  with 1/v correctly rounded.
// rintf = round-half-even = jnp.round.
// ---------------------------------------------------------------------------
__device__ __forceinline__ int voxel_coord(float p, float v, float rinv) {
    float half    = __fmul_rn(v, 0.5f);        // exact
    float shifted = __fsub_rn(p, half);        // IEEE sub
    float q       = __fmul_rn(shifted, rinv);  // multiply by CR reciprocal
    return (int)rintf(q) + 64;
}

__global__ void scatter_kernel(const float* __restrict__ pts_a,
                               const float* __restrict__ pts_b,
                               const float* __restrict__ vs) {
    unsigned idx = blockIdx.x * blockDim.x + threadIdx.x;  // over BATCH*NPTS
    if (idx >= BATCH * NPTS) return;
    const int t = blockIdx.y;
    const float* __restrict__ pts = (t == 0) ? pts_a : pts_b;

    const int b = idx / NPTS;
    const float vx = __ldg(&vs[b * 3 + 0]);
    const float vy = __ldg(&vs[b * 3 + 1]);
    const float vz = __ldg(&vs[b * 3 + 2]);
    const float rx = g_recip[b][0];
    const float ry = g_recip[b][1];
    const float rz = g_recip[b][2];

    const float px = pts[(size_t)idx * 3 + 0];
    const float py = pts[(size_t)idx * 3 + 1];
    const float pz = pts[(size_t)idx * 3 + 2];

    const int i = voxel_coord(px, vx, rx);
    const int j = voxel_coord(py, vy, ry);
    const int k = voxel_coord(pz, vz, rz);

    if ((unsigned)i < NGRID && (unsigned)j < NGRID && (unsigned)k < NGRID) {
        const unsigned lin = (((unsigned)b * NGRID + i) * NGRID + j) * NGRID + k;
        atomicOr(&g_mask[t][lin >> 5], 1u << (lin & 31u));
    }
}

// ---------------------------------------------------------------------------
// Kernel 3: expand bitmasks into the output tensor.
// Warp-strided 4-voxel-per-thread layout: each warp owns 128 CONSECUTIVE
// voxels; element u of each lane hits base + u*32 + lane, so every STG.128
// is lane-contiguous -> full 512 B per instruction (the proven-fast pattern),
// with 4-deep store ILP and 8 broadcast mask LDGs amortized over 4 stores.
// NO mask clears (measured toxic in R4-R6), NO __stwt (regression in R4).
// ---------------------------------------------------------------------------
__global__ void expand_kernel(float4* __restrict__ out,
                              const float* __restrict__ emb) {
    const unsigned gwarp = (blockIdx.x * blockDim.x + threadIdx.x) >> 5;
    const unsigned lane  = threadIdx.x & 31u;
    const unsigned base  = gwarp * 128u;     // first voxel of this warp
    const unsigned w0    = base >> 5;        // first of 4 mask words

    unsigned wa[4], wb[4];
#pragma unroll
    for (int u = 0; u < 4; u++) {
        wa[u] = g_mask[0][w0 + u];           // warp-broadcast loads
        wb[u] = g_mask[1][w0 + u];
    }

    const float e00 = __ldg(&emb[0]);
    const float e01 = __ldg(&emb[1]);
    const float e10 = __ldg(&emb[2]);
    const float e11 = __ldg(&emb[3]);

#pragma unroll
    for (int u = 0; u < 4; u++) {
        const bool a = (wa[u] >> lane) & 1u;
        const bool c = (wb[u] >> lane) & 1u;
        out[base + (unsigned)u * 32u + lane] =
            make_float4(a ? e00 : 0.0f, a ? e01 : 0.0f,
                        c ? e10 : 0.0f, c ? e11 : 0.0f);
    }
}

// ---------------------------------------------------------------------------
// Launch
// Inputs (metadata order): points_a [4,200000,3] f32, points_b [4,200000,3] f32,
//                          neck_voxel_sizes [4,3] f32, embedding_weight [2,2] f32
// Output: [4,128,128,128,4] f32  (33,554,432 floats)
// ---------------------------------------------------------------------------
extern "C" void kernel_launch(void* const* d_in, const int* in_sizes, int n_in,
                              void* d_out, int out_size) {
    const float* pts_a = (const float*)d_in[0];
    const float* pts_b = (const float*)d_in[1];
    const float* vs    = (const float*)d_in[2];
    const float* emb   = (const float*)d_in[3];

    // 1) setup: zero 2 MB mask (131072 uint4) + precompute recips
    setup_kernel<<<131072 / 256, 256>>>(vs);

    // 2) scatter both point sets into the bitmasks
    dim3 sgrid((BATCH * NPTS + 255) / 256, 2);
    scatter_kernel<<<sgrid, 256>>>(pts_a, pts_b, vs);

    // 3) expand: NVOX/4 threads, 4 warp-strided float4 stores each
    expand_kernel<<<(NVOX / 4) / 256, 256>>>((float4*)d_out, emb);
}